// round 12
// baseline (speedup 1.0000x reference)
#include <cuda_runtime.h>
#include <cstdint>

#define THREADS 128
#define NBLOCKS 512     // 128 pb x 2 o-half x 2 c-half

typedef unsigned long long ull;

// scratch: [ch][po*2048 + t*128 + tid] u64 partials (8.4 MB)
__device__ ull g_scratch[2][256 * 2048];

// smem x tile: 16c x 4k x 4q x 8pp granules of 16B = 32 KB
#define GR(c,k,q,pp) ((((c)*4+(k))*4+(q))*8+(pp))

__global__ __launch_bounds__(THREADS, 3)
void lc1d_v9(const float* __restrict__ x, const float* __restrict__ w)
{
    __shared__ __align__(16) float4 xs[2048];   // 32 KB

    const int tid = threadIdx.x;
    const int bx  = blockIdx.x;
    const int ch  = bx & 1;                 // c half
    const int po  = bx >> 1;                // 0..255
    const int oh  = po & 1;                 // o half
    const int pb  = po >> 1;                // patches 8pb..8pb+7
    const int c0  = ch * 16;
    const int obase = oh * 32;

    const int lane = tid & 31;
    const int pp   = lane & 7;
    const int ogl  = lane >> 3;
    const int wrp  = tid >> 5;
    const int ogh  = wrp & 1;
    const int bq   = wrp >> 1;              // batches 8bq..8bq+7
    const int og   = ogh * 4 + ogl;         // o = obase + 4og + i

    const float4* x4 = reinterpret_cast<const float4*>(x);
    const float4* w4 = reinterpret_cast<const float4*>(w);
    const ulonglong2* xsu = reinterpret_cast<const ulonglong2*>(xs);

    // ---- producer: stage 16 c's, transposing k-quads -> b-quads ----
    #pragma unroll
    for (int it = 0; it < 4; ++it) {
        int gi = it * THREADS + tid;        // 0..511
        int g  = gi & 3;                    // b-quad
        int pq = (gi >> 2) & 7;
        int c  = gi >> 5;                   // 0..15
        float4 v0 = x4[(size_t)((4 * g + 0) * 32 + c0 + c) * 1024 + pb * 8 + pq];
        float4 v1 = x4[(size_t)((4 * g + 1) * 32 + c0 + c) * 1024 + pb * 8 + pq];
        float4 v2 = x4[(size_t)((4 * g + 2) * 32 + c0 + c) * 1024 + pb * 8 + pq];
        float4 v3 = x4[(size_t)((4 * g + 3) * 32 + c0 + c) * 1024 + pb * 8 + pq];
        xs[GR(c, 0, g, pq)] = make_float4(v0.x, v1.x, v2.x, v3.x);
        xs[GR(c, 1, g, pq)] = make_float4(v0.y, v1.y, v2.y, v3.y);
        xs[GR(c, 2, g, pq)] = make_float4(v0.z, v1.z, v2.z, v3.z);
        xs[GR(c, 3, g, pq)] = make_float4(v0.w, v1.w, v2.w, v3.w);
    }
    __syncthreads();

    // acc[i*4+bp]: o = obase+4og+i, batches (8bq+2bp, +1) in f32x2 lanes
    ull acc[16];
    #pragma unroll
    for (int t = 0; t < 16; ++t) acc[t] = 0ULL;

    // w granule (16B k-quad): idx = (o*32 + c)*1024 + pb*8 + pp
    const size_t wb = (size_t)(obase + 4 * og) * 32 * 1024 + (size_t)pb * 8 + pp;

    float4 wv[2][4];
    #pragma unroll
    for (int i = 0; i < 4; ++i)
        wv[0][i] = w4[wb + (size_t)(i * 32 + c0) * 1024];

    #pragma unroll
    for (int c = 0; c < 16; ++c) {
        const int cur = c & 1, nxt = cur ^ 1;
        if (c + 1 < 16) {
            #pragma unroll
            for (int i = 0; i < 4; ++i)
                wv[nxt][i] = w4[wb + (size_t)(i * 32 + c0 + c + 1) * 1024];
        }
        #pragma unroll
        for (int k = 0; k < 4; ++k) {
            ulonglong2 g0 = xsu[GR(c, k, 2 * bq, pp)];
            ulonglong2 g1 = xsu[GR(c, k, 2 * bq + 1, pp)];
            const ull xp0 = g0.x, xp1 = g0.y, xp2 = g1.x, xp3 = g1.y;
            #pragma unroll
            for (int i = 0; i < 4; ++i) {
                float wk = (k == 0) ? wv[cur][i].x : (k == 1) ? wv[cur][i].y
                         : (k == 2) ? wv[cur][i].z : wv[cur][i].w;
                ull wd;
                asm("mov.b64 %0, {%1, %1};" : "=l"(wd) : "f"(wk));
                asm("fma.rn.f32x2 %0, %1, %2, %0;" : "+l"(acc[i * 4 + 0]) : "l"(xp0), "l"(wd));
                asm("fma.rn.f32x2 %0, %1, %2, %0;" : "+l"(acc[i * 4 + 1]) : "l"(xp1), "l"(wd));
                asm("fma.rn.f32x2 %0, %1, %2, %0;" : "+l"(acc[i * 4 + 2]) : "l"(xp2), "l"(wd));
                asm("fma.rn.f32x2 %0, %1, %2, %0;" : "+l"(acc[i * 4 + 3]) : "l"(xp3), "l"(wd));
            }
        }
    }

    // ---- store partials: dense 256B warp-stores ----
    ull* dst = &g_scratch[ch][(size_t)po * 2048 + tid];
    #pragma unroll
    for (int t = 0; t < 16; ++t) dst[t * 128] = acc[t];
}

__global__ __launch_bounds__(256)
void lc1d_v9_reduce(float* __restrict__ out)
{
    const int j = blockIdx.x * 256 + threadIdx.x;   // 0..524287
    const ull s0 = g_scratch[0][j];
    const ull s1 = g_scratch[1][j];

    float a0, a1, b0, b1;
    asm("mov.b64 {%0, %1}, %2;" : "=f"(a0), "=f"(a1) : "l"(s0));
    asm("mov.b64 {%0, %1}, %2;" : "=f"(b0), "=f"(b1) : "l"(s1));
    const float sc = 0.17677669529663687f;          // 1/sqrt(32)
    const float lo = (a0 + b0) * sc;
    const float hi = (a1 + b1) * sc;

    // decode j = po*2048 + t*128 + tid1
    const int po   = j >> 11;
    const int r    = j & 2047;
    const int t    = r >> 7;
    const int tid1 = r & 127;
    const int lane = tid1 & 31, wrp = tid1 >> 5;
    const int pp = lane & 7, ogl = lane >> 3;
    const int ogh = wrp & 1, bq = wrp >> 1;
    const int i = t >> 2, bp = t & 3;
    const int pb = po >> 1, oh = po & 1;

    const int o = oh * 32 + (ogh * 4 + ogl) * 4 + i;
    const int p = pb * 8 + pp;
    const int b = 8 * bq + 2 * bp;

    out[(size_t)b * 65536 + (size_t)o * 1024 + p]       = lo;
    out[(size_t)(b + 1) * 65536 + (size_t)o * 1024 + p] = hi;
}

extern "C" void kernel_launch(void* const* d_in, const int* in_sizes, int n_in,
                              void* d_out, int out_size)
{
    const float* x = (const float*)d_in[0];   // [16, 32, 4096]
    const float* w = (const float*)d_in[1];   // [64, 32, 4096]
    float* out = (float*)d_out;               // [16, 64, 1024]
    (void)in_sizes; (void)n_in; (void)out_size;

    lc1d_v9<<<NBLOCKS, THREADS>>>(x, w);
    lc1d_v9_reduce<<<2048, 256>>>(out);
}

// round 14
// speedup vs baseline: 1.0017x; 1.0017x over previous
#include <cuda_runtime.h>
#include <cstdint>

#define THREADS 256
#define NBLOCKS 256     // 128 patch-blocks (8 patches) x 2 o-halves

typedef unsigned long long ull;

// smem x tile (one 16-c pass): 16c x 4k x 4q x 8pp granules of 16B = 32 KB
// granule (c,k,q,pp) = batches {4q..4q+3} at (c0+c, patch pp, k)
#define GR(c,k,q,pp) ((((c)*4+(k))*4+(q))*8+(pp))

__global__ __launch_bounds__(THREADS, 2)
void lc1d_v11(const float* __restrict__ x,
              const float* __restrict__ w,
              float* __restrict__ out)
{
    __shared__ __align__(16) float4 xs[2048];   // 32 KB

    const int tid   = threadIdx.x;
    const int pb    = blockIdx.x >> 1;          // patches 8pb..8pb+7
    const int obase = (blockIdx.x & 1) * 32;

    const int lane = tid & 31;
    const int pp   = lane & 7;                  // fast lane dim -> dense w lines
    const int bql  = lane >> 3;                 // batch quad 4bql..4bql+3
    const int ow   = tid >> 5;                  // warp = o group; o = obase+4ow+i

    const float4* x4 = reinterpret_cast<const float4*>(x);
    const float4* w4 = reinterpret_cast<const float4*>(w);
    const ulonglong2* xsu = reinterpret_cast<const ulonglong2*>(xs);

    // acc[i*2+h]: o = obase+4ow+i, batches (4bql+2h, 4bql+2h+1) in f32x2 lanes
    ull acc[8];
    #pragma unroll
    for (int t = 0; t < 8; ++t) acc[t] = 0ULL;

    // w granule (16B k-quad): idx = (o*32 + c)*1024 + pb*8 + pp
    const size_t wb = (size_t)(obase + 4 * ow) * 32768 + (size_t)pb * 8 + pp;

    #pragma unroll
    for (int pass = 0; pass < 2; ++pass) {
        const int c0 = pass * 16;
        if (pass) __syncthreads();              // prior consumer done with xs

        // ---- producer: stage 16 c, transposing k-quads -> b-quads ----
        #pragma unroll
        for (int it = 0; it < 2; ++it) {
            int gi = it * THREADS + tid;        // 0..511
            int g  = gi & 3;                    // b-quad
            int pq = (gi >> 2) & 7;
            int c  = gi >> 5;                   // 0..15
            float4 v0 = x4[(size_t)((4 * g + 0) * 32 + c0 + c) * 1024 + pb * 8 + pq];
            float4 v1 = x4[(size_t)((4 * g + 1) * 32 + c0 + c) * 1024 + pb * 8 + pq];
            float4 v2 = x4[(size_t)((4 * g + 2) * 32 + c0 + c) * 1024 + pb * 8 + pq];
            float4 v3 = x4[(size_t)((4 * g + 3) * 32 + c0 + c) * 1024 + pb * 8 + pq];
            xs[GR(c, 0, g, pq)] = make_float4(v0.x, v1.x, v2.x, v3.x);
            xs[GR(c, 1, g, pq)] = make_float4(v0.y, v1.y, v2.y, v3.y);
            xs[GR(c, 2, g, pq)] = make_float4(v0.z, v1.z, v2.z, v3.z);
            xs[GR(c, 3, g, pq)] = make_float4(v0.w, v1.w, v2.w, v3.w);
        }
        __syncthreads();

        // ---- consumer: 16 c, distance-2 w prefetch (3-slot buffer) ----
        float4 wv[3][4];
        #pragma unroll
        for (int i = 0; i < 4; ++i) {
            wv[0][i] = w4[wb + (size_t)(i * 32 + c0 + 0) * 1024];
            wv[1][i] = w4[wb + (size_t)(i * 32 + c0 + 1) * 1024];
        }

        #pragma unroll
        for (int c = 0; c < 16; ++c) {
            const int s = c % 3;
            if (c + 2 < 16) {
                const int sn = (c + 2) % 3;
                #pragma unroll
                for (int i = 0; i < 4; ++i)
                    wv[sn][i] = w4[wb + (size_t)(i * 32 + c0 + c + 2) * 1024];
            }
            #pragma unroll
            for (int k = 0; k < 4; ++k) {
                // this thread's 4 batches: one dense granule (512B/warp)
                const ulonglong2 gq = xsu[GR(c, k, bql, pp)];
                const ull xp0 = gq.x, xp1 = gq.y;
                #pragma unroll
                for (int i = 0; i < 4; ++i) {
                    float wk = (k == 0) ? wv[s][i].x : (k == 1) ? wv[s][i].y
                             : (k == 2) ? wv[s][i].z : wv[s][i].w;
                    ull wd;
                    asm("mov.b64 %0, {%1, %1};" : "=l"(wd) : "f"(wk));
                    asm("fma.rn.f32x2 %0, %1, %2, %0;" : "+l"(acc[i * 2 + 0]) : "l"(xp0), "l"(wd));
                    asm("fma.rn.f32x2 %0, %1, %2, %0;" : "+l"(acc[i * 2 + 1]) : "l"(xp1), "l"(wd));
                }
            }
        }
    }

    // ---- epilogue: scale and store ----
    const float sc = 0.17677669529663687f;   // 1/sqrt(32)
    const int p = pb * 8 + pp;
    #pragma unroll
    for (int i = 0; i < 4; ++i) {
        const int o = obase + 4 * ow + i;
        #pragma unroll
        for (int h = 0; h < 2; ++h) {
            float lo, hi;
            asm("mov.b64 {%0, %1}, %2;" : "=f"(lo), "=f"(hi) : "l"(acc[i * 2 + h]));
            const int b = 4 * bql + 2 * h;
            out[(size_t)b * 65536 + (size_t)o * 1024 + p]       = lo * sc;
            out[(size_t)(b + 1) * 65536 + (size_t)o * 1024 + p] = hi * sc;
        }
    }
}

extern "C" void kernel_launch(void* const* d_in, const int* in_sizes, int n_in,
                              void* d_out, int out_size)
{
    const float* x = (const float*)d_in[0];   // [16, 32, 4096]
    const float* w = (const float*)d_in[1];   // [64, 32, 4096]
    float* out = (float*)d_out;               // [16, 64, 1024]
    (void)in_sizes; (void)n_in; (void)out_size;

    lc1d_v11<<<NBLOCKS, THREADS>>>(x, w, out);
}

// round 15
// speedup vs baseline: 1.0169x; 1.0153x over previous
#include <cuda_runtime.h>
#include <cstdint>

#define THREADS 256
#define NBLOCKS 512   // 128 pb x 2 o-half x 2 b-half

typedef unsigned long long ull;

// x tile: granule(c,k,bq,pp) 16B = b-quad {8bh+4bq..+3} at (c, patch pp, k)
// idx = ((c*4+k)*2+bq)*8+pp ; 2048 granules = 32 KB
#define GR(c,k,bq,pp) ((((c)*4+(k))*2+(bq))*8+(pp))

__global__ __launch_bounds__(THREADS, 3)
void lc1d_v13(const float* __restrict__ x,
              const float* __restrict__ w,
              float* __restrict__ out)
{
    __shared__ __align__(16) float4 xs[2048];   // 32 KB

    const int tid = threadIdx.x;
    const int bx  = blockIdx.x;
    const int pb  = bx >> 2;                    // patches 8pb..8pb+7
    const int oh  = (bx >> 1) & 1;              // o half
    const int bh  = bx & 1;                     // b half: b in [8bh, 8bh+8)

    const int lane = tid & 31;
    const int pp   = lane & 7;                  // fast -> dense lines / contiguous LDS
    const int oL   = lane >> 3;                 // 0..3
    const int wid  = tid >> 5;
    const int ow   = wid >> 1;                  // 0..3
    const int ch   = wid & 1;                   // c half handled by this warp

    const float4* x4 = reinterpret_cast<const float4*>(x);
    const float4* w4 = reinterpret_cast<const float4*>(w);
    const ulonglong2* xsu = reinterpret_cast<const ulonglong2*>(xs);

    // ---- producer: stage x tile (b-half), transposing k-quads -> b-quads ----
    #pragma unroll
    for (int it = 0; it < 2; ++it) {
        int gi = it * THREADS + tid;            // 0..511
        int bq = gi & 1;
        int pq = (gi >> 1) & 7;
        int c  = gi >> 4;                       // 0..31
        int b0 = 8 * bh + 4 * bq;
        float4 v0 = x4[(size_t)((b0 + 0) * 32 + c) * 1024 + pb * 8 + pq];
        float4 v1 = x4[(size_t)((b0 + 1) * 32 + c) * 1024 + pb * 8 + pq];
        float4 v2 = x4[(size_t)((b0 + 2) * 32 + c) * 1024 + pb * 8 + pq];
        float4 v3 = x4[(size_t)((b0 + 3) * 32 + c) * 1024 + pb * 8 + pq];
        xs[GR(c, 0, bq, pq)] = make_float4(v0.x, v1.x, v2.x, v3.x);
        xs[GR(c, 1, bq, pq)] = make_float4(v0.y, v1.y, v2.y, v3.y);
        xs[GR(c, 2, bq, pq)] = make_float4(v0.z, v1.z, v2.z, v3.z);
        xs[GR(c, 3, bq, pq)] = make_float4(v0.w, v1.w, v2.w, v3.w);
    }
    __syncthreads();

    // acc[i*4 + bq*2 + h]: o = oh*32+ow*8+oL*2+i, batches (8bh+4bq+2h, +1)
    ull acc[8];
    #pragma unroll
    for (int t = 0; t < 8; ++t) acc[t] = 0ULL;

    // w granule (16B k-quad): idx = (o*32 + c)*1024 + pb*8 + pp
    const int c0 = ch * 16;
    const size_t wb = (size_t)(oh * 32 + ow * 8 + oL * 2) * 32768 + (size_t)pb * 8 + pp;

    // distance-2 prefetch, 3-slot buffer, 2 o's per slot
    float4 wv[3][2];
    #pragma unroll
    for (int i = 0; i < 2; ++i) {
        wv[0][i] = w4[wb + (size_t)(i * 32 + c0 + 0) * 1024];
        wv[1][i] = w4[wb + (size_t)(i * 32 + c0 + 1) * 1024];
    }

    #pragma unroll
    for (int cc = 0; cc < 16; ++cc) {
        const int c = c0 + cc;
        const int s = cc % 3;
        if (cc + 2 < 16) {
            const int sn = (cc + 2) % 3;
            #pragma unroll
            for (int i = 0; i < 2; ++i)
                wv[sn][i] = w4[wb + (size_t)(i * 32 + c + 2) * 1024];
        }
        #pragma unroll
        for (int k = 0; k < 4; ++k) {
            // 2 b-quads, each one broadcast-contiguous LDS.128 (1 wf)
            const ulonglong2 g0 = xsu[GR(c, k, 0, pp)];
            const ulonglong2 g1 = xsu[GR(c, k, 1, pp)];
            #pragma unroll
            for (int i = 0; i < 2; ++i) {
                float wk = (k == 0) ? wv[s][i].x : (k == 1) ? wv[s][i].y
                         : (k == 2) ? wv[s][i].z : wv[s][i].w;
                ull wd;
                asm("mov.b64 %0, {%1, %1};" : "=l"(wd) : "f"(wk));
                asm("fma.rn.f32x2 %0, %1, %2, %0;" : "+l"(acc[i * 4 + 0]) : "l"(g0.x), "l"(wd));
                asm("fma.rn.f32x2 %0, %1, %2, %0;" : "+l"(acc[i * 4 + 1]) : "l"(g0.y), "l"(wd));
                asm("fma.rn.f32x2 %0, %1, %2, %0;" : "+l"(acc[i * 4 + 2]) : "l"(g1.x), "l"(wd));
                asm("fma.rn.f32x2 %0, %1, %2, %0;" : "+l"(acc[i * 4 + 3]) : "l"(g1.y), "l"(wd));
            }
        }
    }

    // ---- c-half reduction: ch=1 stores partials, ch=0 adds ----
    __syncthreads();                            // xs free for reuse
    ull* rb = reinterpret_cast<ull*>(xs);       // 4ow x 8t x 32lane u64 = 8 KB
    if (ch == 1) {
        #pragma unroll
        for (int t = 0; t < 8; ++t)
            rb[(ow * 8 + t) * 32 + lane] = acc[t];
    }
    __syncthreads();
    if (ch == 0) {
        #pragma unroll
        for (int t = 0; t < 8; ++t) {
            const ull v = rb[(ow * 8 + t) * 32 + lane];
            asm("add.rn.f32x2 %0, %0, %1;" : "+l"(acc[t]) : "l"(v));
        }

        // ---- epilogue: scale and store ----
        const float sc = 0.17677669529663687f;  // 1/sqrt(32)
        const int p = pb * 8 + pp;
        #pragma unroll
        for (int i = 0; i < 2; ++i) {
            const int o = oh * 32 + ow * 8 + oL * 2 + i;
            #pragma unroll
            for (int bq = 0; bq < 2; ++bq) {
                #pragma unroll
                for (int h = 0; h < 2; ++h) {
                    float lo, hi;
                    asm("mov.b64 {%0, %1}, %2;"
                        : "=f"(lo), "=f"(hi) : "l"(acc[i * 4 + bq * 2 + h]));
                    const int b = 8 * bh + 4 * bq + 2 * h;
                    out[(size_t)b * 65536 + (size_t)o * 1024 + p]       = lo * sc;
                    out[(size_t)(b + 1) * 65536 + (size_t)o * 1024 + p] = hi * sc;
                }
            }
        }
    }
}

extern "C" void kernel_launch(void* const* d_in, const int* in_sizes, int n_in,
                              void* d_out, int out_size)
{
    const float* x = (const float*)d_in[0];   // [16, 32, 4096]
    const float* w = (const float*)d_in[1];   // [64, 32, 4096]
    float* out = (float*)d_out;               // [16, 64, 1024]
    (void)in_sizes; (void)n_in; (void)out_size;

    lc1d_v13<<<NBLOCKS, THREADS>>>(x, w, out);
}